// round 1
// baseline (speedup 1.0000x reference)
#include <cuda_runtime.h>

#define T_STEPS  1024
#define F_FEAT   2048
#define LATENT   128
#define ODE_H    256
#define NG       3          // 3*LATENT gate rows
#define G        16         // features per CTA
#define NTHREADS 256
#define NCTAS    (F_FEAT / G)   // 128

__global__ __launch_bounds__(NTHREADS, 1)
void ode_rnn_kernel(const float* __restrict__ times,
                    const float* __restrict__ vals,
                    const float* __restrict__ mask,
                    const float* __restrict__ W1,  const float* __restrict__ b1,
                    const float* __restrict__ W2,  const float* __restrict__ b2,
                    const float* __restrict__ W_ih,const float* __restrict__ b_ih,
                    const float* __restrict__ W_hh,const float* __restrict__ b_hh,
                    float* __restrict__ out)
{
    // h state: 16 features x 128 latent (8 KB)
    __shared__ __align__(16) float h_s[G][LATENT];
    // pool reused: phase1/2 -> t1 (16x256), phase3 -> gh (16x384). 24 KB.
    __shared__ __align__(16) float pool_s[G * NG * LATENT];
    __shared__ float obs_s[G];
    __shared__ float m_s[G];

    const int tid = threadIdx.x;
    const int f0  = blockIdx.x * G;

    // init h = 0
    for (int idx = tid; idx < G * LATENT; idx += NTHREADS)
        (&h_s[0][0])[idx] = 0.0f;
    __syncthreads();

    for (int i = 0; i < T_STEPS; ++i) {
        const int row = T_STEPS - 1 - i;            // reversed sequence
        float dt = 0.0f;
        if (i > 0) dt = __ldg(times + row + 1) - __ldg(times + row);

        // stage observations/mask for this step (used only after later syncs)
        if (tid < G) {
            obs_s[tid] = __ldg(vals + (long)row * F_FEAT + f0 + tid);
            m_s[tid]   = __ldg(mask + (long)row * F_FEAT + f0 + tid);
        }

        if (dt > 0.0f) {
            // ---- Phase 1: t1[g][j] = tanh(b1[j] + sum_k h[g][k]*W1[j][k]), j=tid ----
            {
                const int j = tid;
                float acc[G];
                const float bj = __ldg(b1 + j);
                #pragma unroll
                for (int g = 0; g < G; ++g) acc[g] = bj;
                const float4* wrow = (const float4*)(W1 + j * LATENT);
                #pragma unroll 4
                for (int k4 = 0; k4 < LATENT / 4; ++k4) {
                    const float4 w = __ldg(wrow + k4);
                    #pragma unroll
                    for (int g = 0; g < G; ++g) {
                        const float4 hv = ((const float4*)h_s[g])[k4];
                        acc[g] = fmaf(hv.x, w.x, acc[g]);
                        acc[g] = fmaf(hv.y, w.y, acc[g]);
                        acc[g] = fmaf(hv.z, w.z, acc[g]);
                        acc[g] = fmaf(hv.w, w.w, acc[g]);
                    }
                }
                #pragma unroll
                for (int g = 0; g < G; ++g)
                    pool_s[g * ODE_H + j] = tanhf(acc[g]);   // t1
            }
            __syncthreads();

            // ---- Phase 2: h[g][j] += dt * (b2[j] + sum_k t1[g][k]*W2[j][k]) ----
            // 256 threads: j = tid&127, each half of threads covers 8 features
            {
                const int j  = tid & (LATENT - 1);
                const int g0 = (tid >> 7) * (G / 2);
                float acc[G / 2];
                const float bj = __ldg(b2 + j);
                #pragma unroll
                for (int g = 0; g < G / 2; ++g) acc[g] = bj;
                const float4* wrow = (const float4*)(W2 + j * ODE_H);
                #pragma unroll 4
                for (int k4 = 0; k4 < ODE_H / 4; ++k4) {
                    const float4 w = __ldg(wrow + k4);
                    #pragma unroll
                    for (int g = 0; g < G / 2; ++g) {
                        const float4 tv = ((const float4*)(pool_s + (g0 + g) * ODE_H))[k4];
                        acc[g] = fmaf(tv.x, w.x, acc[g]);
                        acc[g] = fmaf(tv.y, w.y, acc[g]);
                        acc[g] = fmaf(tv.z, w.z, acc[g]);
                        acc[g] = fmaf(tv.w, w.w, acc[g]);
                    }
                }
                #pragma unroll
                for (int g = 0; g < G / 2; ++g)
                    h_s[g0 + g][j] = fmaf(dt, acc[g], h_s[g0 + g][j]);
            }
            __syncthreads();
        }

        // ---- Phase 3: gh[g][j] = b_hh[j] + sum_k h[g][k]*W_hh[j][k], j in [0,384) ----
        {   // 3a: j = tid covers [0,256)
            const int j = tid;
            float acc[G];
            const float bj = __ldg(b_hh + j);
            #pragma unroll
            for (int g = 0; g < G; ++g) acc[g] = bj;
            const float4* wrow = (const float4*)(W_hh + j * LATENT);
            #pragma unroll 4
            for (int k4 = 0; k4 < LATENT / 4; ++k4) {
                const float4 w = __ldg(wrow + k4);
                #pragma unroll
                for (int g = 0; g < G; ++g) {
                    const float4 hv = ((const float4*)h_s[g])[k4];
                    acc[g] = fmaf(hv.x, w.x, acc[g]);
                    acc[g] = fmaf(hv.y, w.y, acc[g]);
                    acc[g] = fmaf(hv.z, w.z, acc[g]);
                    acc[g] = fmaf(hv.w, w.w, acc[g]);
                }
            }
            #pragma unroll
            for (int g = 0; g < G; ++g)
                pool_s[g * (NG * LATENT) + j] = acc[g];      // gh
        }
        {   // 3b: j = 256 + (tid&127), each half of threads covers 8 features
            const int j  = 2 * LATENT + (tid & (LATENT - 1));
            const int g0 = (tid >> 7) * (G / 2);
            float acc[G / 2];
            const float bj = __ldg(b_hh + j);
            #pragma unroll
            for (int g = 0; g < G / 2; ++g) acc[g] = bj;
            const float4* wrow = (const float4*)(W_hh + j * LATENT);
            #pragma unroll 4
            for (int k4 = 0; k4 < LATENT / 4; ++k4) {
                const float4 w = __ldg(wrow + k4);
                #pragma unroll
                for (int g = 0; g < G / 2; ++g) {
                    const float4 hv = ((const float4*)h_s[g0 + g])[k4];
                    acc[g] = fmaf(hv.x, w.x, acc[g]);
                    acc[g] = fmaf(hv.y, w.y, acc[g]);
                    acc[g] = fmaf(hv.z, w.z, acc[g]);
                    acc[g] = fmaf(hv.w, w.w, acc[g]);
                }
            }
            #pragma unroll
            for (int g = 0; g < G / 2; ++g)
                pool_s[(g0 + g) * (NG * LATENT) + j] = acc[g];
        }
        __syncthreads();

        // ---- Update: GRU gates + mask mix, 2048 (g,l) elems, 8 per thread ----
        #pragma unroll
        for (int rep = 0; rep < (G * LATENT) / NTHREADS; ++rep) {
            const int idx = rep * NTHREADS + tid;
            const int g = idx >> 7;
            const int l = idx & (LATENT - 1);
            const float obs = obs_s[g];
            const float m   = m_s[g];
            const float* ghp = pool_s + g * (NG * LATENT);
            const float ir = fmaf(obs, __ldg(W_ih + l),              __ldg(b_ih + l))              + ghp[l];
            const float iz = fmaf(obs, __ldg(W_ih + LATENT + l),     __ldg(b_ih + LATENT + l))     + ghp[LATENT + l];
            const float inn= fmaf(obs, __ldg(W_ih + 2 * LATENT + l), __ldg(b_ih + 2 * LATENT + l));
            const float hn = ghp[2 * LATENT + l];
            const float r  = 1.0f / (1.0f + expf(-ir));
            const float z  = 1.0f / (1.0f + expf(-iz));
            const float n  = tanhf(fmaf(r, hn, inn));
            const float h  = h_s[g][l];
            const float hc = fmaf(z, h - n, n);          // (1-z)*n + z*h
            h_s[g][l] = fmaf(m, hc - h, h);              // m*hc + (1-m)*h
        }
        __syncthreads();
    }

    // write final h: out[(f0+g)*LATENT + l]
    for (int idx = tid; idx < G * LATENT; idx += NTHREADS) {
        const int g = idx >> 7;
        const int l = idx & (LATENT - 1);
        out[(long)(f0 + g) * LATENT + l] = h_s[g][l];
    }
}

extern "C" void kernel_launch(void* const* d_in, const int* in_sizes, int n_in,
                              void* d_out, int out_size)
{
    (void)in_sizes; (void)n_in; (void)out_size;
    const float* times = (const float*)d_in[0];
    const float* vals  = (const float*)d_in[1];
    const float* mask  = (const float*)d_in[2];
    const float* W1    = (const float*)d_in[3];
    const float* b1    = (const float*)d_in[4];
    const float* W2    = (const float*)d_in[5];
    const float* b2    = (const float*)d_in[6];
    const float* W_ih  = (const float*)d_in[7];
    const float* b_ih  = (const float*)d_in[8];
    const float* W_hh  = (const float*)d_in[9];
    const float* b_hh  = (const float*)d_in[10];
    float* out = (float*)d_out;

    ode_rnn_kernel<<<NCTAS, NTHREADS>>>(times, vals, mask,
                                        W1, b1, W2, b2,
                                        W_ih, b_ih, W_hh, b_hh, out);
}

// round 2
// speedup vs baseline: 1.8483x; 1.8483x over previous
#include <cuda_runtime.h>

#define T_STEPS  1024
#define F_FEAT   2048
#define LATENT   128
#define ODE_H    256
#define GR       384          // 3*LATENT gate rows
#define G        16           // features per CTA
#define GP       8            // feature pairs per CTA
#define NTHREADS 256
#define NCTAS    (F_FEAT / G) // 128

typedef unsigned long long u64;

// ---------- packed f32x2 helpers ----------
__device__ __forceinline__ u64 ffma2(u64 a, u64 b, u64 c) {
    u64 d;
    asm("fma.rn.f32x2 %0, %1, %2, %3;" : "=l"(d) : "l"(a), "l"(b), "l"(c));
    return d;
}
__device__ __forceinline__ u64 dup2(float x) {
    u64 r;
    asm("mov.b64 %0, {%1, %1};" : "=l"(r) : "f"(x));
    return r;
}
__device__ __forceinline__ float2 unpk(u64 v) {
    float2 r;
    asm("mov.b64 {%0, %1}, %2;" : "=f"(r.x), "=f"(r.y) : "l"(v));
    return r;
}
__device__ __forceinline__ u64 pack2(float x, float y) {
    u64 r;
    asm("mov.b64 %0, {%1, %2};" : "=l"(r) : "f"(x), "f"(y));
    return r;
}
__device__ __forceinline__ float fast_sigmoid(float x) {
    return __fdividef(1.0f, 1.0f + __expf(-x));
}

// ---------- repacked (transposed) weights: coalesced mainloop loads ----------
// g_W1p[k4*256 + j] = float4 of W1[j][4k4..4k4+3]      (k4<32,  j<256)
// g_W2p[k4*128 + j] = float4 of W2[j][4k4..4k4+3]      (k4<64,  j<128)
// g_Whp[k4*384 + j] = float4 of W_hh[j][4k4..4k4+3]    (k4<32,  j<384)
__device__ float4 g_W1p[32 * 256];
__device__ float4 g_W2p[64 * 128];
__device__ float4 g_Whp[32 * 384];

__global__ void repack_kernel(const float* __restrict__ W1,
                              const float* __restrict__ W2,
                              const float* __restrict__ Whh)
{
    int i = blockIdx.x * blockDim.x + threadIdx.x;
    if (i < 32 * 256) {
        int k4 = i >> 8, j = i & 255;
        g_W1p[k4 * 256 + j] = *(const float4*)(W1 + j * LATENT + 4 * k4);
    } else if (i < 32 * 256 + 64 * 128) {
        int t = i - 32 * 256;
        int k4 = t >> 7, j = t & 127;
        g_W2p[k4 * 128 + j] = *(const float4*)(W2 + j * ODE_H + 4 * k4);
    } else if (i < 32 * 256 + 64 * 128 + 32 * 384) {
        int t = i - (32 * 256 + 64 * 128);
        int k4 = t / 384, j = t % 384;
        g_Whp[k4 * 384 + j] = *(const float4*)(Whh + j * LATENT + 4 * k4);
    }
}

// ---------- main persistent recurrence kernel ----------
__global__ __launch_bounds__(NTHREADS, 1)
void ode_rnn_kernel(const float* __restrict__ times,
                    const float* __restrict__ vals,
                    const float* __restrict__ mask,
                    const float* __restrict__ b1,
                    const float* __restrict__ b2,
                    const float* __restrict__ W_ih,
                    const float* __restrict__ b_ih,
                    const float* __restrict__ b_hh,
                    float* __restrict__ out)
{
    // h stored as interleaved feature pairs: hp[p*128 + k] = {h[2p][k], h[2p+1][k]}
    __shared__ __align__(16) u64 hp[GP * LATENT];          // 8 KB
    // pool reused: phase1 -> t1 pairs [p*256 + j]; phase3 -> gh pairs [p*384 + j]
    __shared__ __align__(16) u64 pool[GP * GR];            // 24 KB
    __shared__ float2 obs2[GP];
    __shared__ float2 m2[GP];

    const int tid = threadIdx.x;
    const int f0  = blockIdx.x * G;

    for (int idx = tid; idx < GP * LATENT; idx += NTHREADS)
        hp[idx] = 0ULL;
    __syncthreads();

    for (int i = 0; i < T_STEPS; ++i) {
        const int row = T_STEPS - 1 - i;               // reversed sequence
        float dt = 0.0f;
        if (i > 0) dt = __ldg(times + row + 1) - __ldg(times + row);

        // stage observations / mask for this step (read in update phase after syncs)
        if (tid < GP) {
            obs2[tid] = __ldg((const float2*)(vals + (long)row * F_FEAT + f0) + tid);
            m2[tid]   = __ldg((const float2*)(mask + (long)row * F_FEAT + f0) + tid);
        }

        if (dt > 0.0f) {
            // ---- Phase 1: t1[p][j] = tanh(b1[j] + sum_k h2[p][k]*W1[j][k]), j = tid ----
            {
                const int j = tid;
                u64 acc[GP];
                const u64 bj = dup2(__ldg(b1 + j));
                #pragma unroll
                for (int p = 0; p < GP; ++p) acc[p] = bj;
                const float4* wrow = g_W1p + j;
                #pragma unroll 2
                for (int k4 = 0; k4 < LATENT / 4; ++k4) {
                    const float4 w = __ldg(wrow + k4 * ODE_H);
                    const u64 w0 = dup2(w.x), w1 = dup2(w.y);
                    const u64 w2 = dup2(w.z), w3 = dup2(w.w);
                    #pragma unroll
                    for (int p = 0; p < GP; ++p) {
                        const ulonglong2* hv = (const ulonglong2*)(hp + p * LATENT);
                        const ulonglong2 a = hv[2 * k4];
                        const ulonglong2 b = hv[2 * k4 + 1];
                        acc[p] = ffma2(a.x, w0, acc[p]);
                        acc[p] = ffma2(a.y, w1, acc[p]);
                        acc[p] = ffma2(b.x, w2, acc[p]);
                        acc[p] = ffma2(b.y, w3, acc[p]);
                    }
                }
                #pragma unroll
                for (int p = 0; p < GP; ++p) {
                    const float2 v = unpk(acc[p]);
                    pool[p * ODE_H + j] = pack2(tanhf(v.x), tanhf(v.y));
                }
            }
            __syncthreads();

            // ---- Phase 2: h2[p][j] += dt * (b2[j] + sum_k t1[p][k]*W2[j][k]) ----
            {
                const int j  = tid & (LATENT - 1);
                const int p0 = (tid >> 7) * 4;
                u64 acc[4];
                const u64 bj = dup2(__ldg(b2 + j));
                #pragma unroll
                for (int p = 0; p < 4; ++p) acc[p] = bj;
                const float4* wrow = g_W2p + j;
                #pragma unroll 4
                for (int k4 = 0; k4 < ODE_H / 4; ++k4) {
                    const float4 w = __ldg(wrow + k4 * LATENT);
                    const u64 w0 = dup2(w.x), w1 = dup2(w.y);
                    const u64 w2 = dup2(w.z), w3 = dup2(w.w);
                    #pragma unroll
                    for (int p = 0; p < 4; ++p) {
                        const ulonglong2* tv = (const ulonglong2*)(pool + (p0 + p) * ODE_H);
                        const ulonglong2 a = tv[2 * k4];
                        const ulonglong2 b = tv[2 * k4 + 1];
                        acc[p] = ffma2(a.x, w0, acc[p]);
                        acc[p] = ffma2(a.y, w1, acc[p]);
                        acc[p] = ffma2(b.x, w2, acc[p]);
                        acc[p] = ffma2(b.y, w3, acc[p]);
                    }
                }
                const u64 dt2 = dup2(dt);
                #pragma unroll
                for (int p = 0; p < 4; ++p)
                    hp[(p0 + p) * LATENT + j] = ffma2(acc[p], dt2, hp[(p0 + p) * LATENT + j]);
            }
            __syncthreads();
        }

        // ---- Phase 3a: gh[p][j] = b_hh[j] + sum_k h2[p][k]*W_hh[j][k], j = tid (<256) ----
        {
            const int j = tid;
            u64 acc[GP];
            const u64 bj = dup2(__ldg(b_hh + j));
            #pragma unroll
            for (int p = 0; p < GP; ++p) acc[p] = bj;
            const float4* wrow = g_Whp + j;
            #pragma unroll 2
            for (int k4 = 0; k4 < LATENT / 4; ++k4) {
                const float4 w = __ldg(wrow + k4 * GR);
                const u64 w0 = dup2(w.x), w1 = dup2(w.y);
                const u64 w2 = dup2(w.z), w3 = dup2(w.w);
                #pragma unroll
                for (int p = 0; p < GP; ++p) {
                    const ulonglong2* hv = (const ulonglong2*)(hp + p * LATENT);
                    const ulonglong2 a = hv[2 * k4];
                    const ulonglong2 b = hv[2 * k4 + 1];
                    acc[p] = ffma2(a.x, w0, acc[p]);
                    acc[p] = ffma2(a.y, w1, acc[p]);
                    acc[p] = ffma2(b.x, w2, acc[p]);
                    acc[p] = ffma2(b.y, w3, acc[p]);
                }
            }
            #pragma unroll
            for (int p = 0; p < GP; ++p)
                pool[p * GR + j] = acc[p];
        }
        // ---- Phase 3b: rows 256..383, j = 256 + (tid&127), gp half-split ----
        {
            const int j  = 2 * LATENT + (tid & (LATENT - 1));
            const int p0 = (tid >> 7) * 4;
            u64 acc[4];
            const u64 bj = dup2(__ldg(b_hh + j));
            #pragma unroll
            for (int p = 0; p < 4; ++p) acc[p] = bj;
            const float4* wrow = g_Whp + j;
            #pragma unroll 4
            for (int k4 = 0; k4 < LATENT / 4; ++k4) {
                const float4 w = __ldg(wrow + k4 * GR);
                const u64 w0 = dup2(w.x), w1 = dup2(w.y);
                const u64 w2 = dup2(w.z), w3 = dup2(w.w);
                #pragma unroll
                for (int p = 0; p < 4; ++p) {
                    const ulonglong2* hv = (const ulonglong2*)(hp + (p0 + p) * LATENT);
                    const ulonglong2 a = hv[2 * k4];
                    const ulonglong2 b = hv[2 * k4 + 1];
                    acc[p] = ffma2(a.x, w0, acc[p]);
                    acc[p] = ffma2(a.y, w1, acc[p]);
                    acc[p] = ffma2(b.x, w2, acc[p]);
                    acc[p] = ffma2(b.y, w3, acc[p]);
                }
            }
            #pragma unroll
            for (int p = 0; p < 4; ++p)
                pool[(p0 + p) * GR + j] = acc[p];
        }
        __syncthreads();

        // ---- Update: GRU gates + mask mix over 1024 (pair, l) elements ----
        #pragma unroll
        for (int rep = 0; rep < (GP * LATENT) / NTHREADS; ++rep) {
            const int idx = rep * NTHREADS + tid;
            const int p = idx >> 7;
            const int l = idx & (LATENT - 1);
            const float2 gr = unpk(pool[p * GR + l]);
            const float2 gz = unpk(pool[p * GR + LATENT + l]);
            const float2 gn = unpk(pool[p * GR + 2 * LATENT + l]);
            const float2 ob = obs2[p];
            const float2 mm = m2[p];
            const float2 h  = unpk(hp[p * LATENT + l]);
            const float wr = __ldg(W_ih + l);
            const float wz = __ldg(W_ih + LATENT + l);
            const float wn = __ldg(W_ih + 2 * LATENT + l);
            const float br = __ldg(b_ih + l);
            const float bz = __ldg(b_ih + LATENT + l);
            const float bn = __ldg(b_ih + 2 * LATENT + l);

            // component x
            const float rX = fast_sigmoid(fmaf(ob.x, wr, br) + gr.x);
            const float zX = fast_sigmoid(fmaf(ob.x, wz, bz) + gz.x);
            const float nX = tanhf(fmaf(ob.x, wn, bn) + rX * gn.x);
            const float hcX = fmaf(zX, h.x - nX, nX);
            const float hX  = fmaf(mm.x, hcX - h.x, h.x);
            // component y
            const float rY = fast_sigmoid(fmaf(ob.y, wr, br) + gr.y);
            const float zY = fast_sigmoid(fmaf(ob.y, wz, bz) + gz.y);
            const float nY = tanhf(fmaf(ob.y, wn, bn) + rY * gn.y);
            const float hcY = fmaf(zY, h.y - nY, nY);
            const float hY  = fmaf(mm.y, hcY - h.y, h.y);

            hp[p * LATENT + l] = pack2(hX, hY);
        }
        __syncthreads();
    }

    // write final h: out[(f0 + g)*LATENT + l]
    for (int idx = tid; idx < GP * LATENT; idx += NTHREADS) {
        const int p = idx >> 7;
        const int l = idx & (LATENT - 1);
        const float2 v = unpk(hp[idx]);
        out[(long)(f0 + 2 * p)     * LATENT + l] = v.x;
        out[(long)(f0 + 2 * p + 1) * LATENT + l] = v.y;
    }
}

extern "C" void kernel_launch(void* const* d_in, const int* in_sizes, int n_in,
                              void* d_out, int out_size)
{
    (void)in_sizes; (void)n_in; (void)out_size;
    const float* times = (const float*)d_in[0];
    const float* vals  = (const float*)d_in[1];
    const float* mask  = (const float*)d_in[2];
    const float* W1    = (const float*)d_in[3];
    const float* b1    = (const float*)d_in[4];
    const float* W2    = (const float*)d_in[5];
    const float* b2    = (const float*)d_in[6];
    const float* W_ih  = (const float*)d_in[7];
    const float* b_ih  = (const float*)d_in[8];
    const float* W_hh  = (const float*)d_in[9];
    const float* b_hh  = (const float*)d_in[10];
    float* out = (float*)d_out;

    const int total = 32 * 256 + 64 * 128 + 32 * 384;
    repack_kernel<<<(total + 255) / 256, 256>>>(W1, W2, W_hh);
    ode_rnn_kernel<<<NCTAS, NTHREADS>>>(times, vals, mask,
                                        b1, b2, W_ih, b_ih, b_hh, out);
}

// round 3
// speedup vs baseline: 2.0294x; 1.0980x over previous
#include <cuda_runtime.h>

#define T_STEPS  1024
#define F_FEAT   2048
#define LATENT   128
#define ODE_H    256
#define GR       384          // 3*LATENT gate rows
#define G        16           // features per CTA
#define GP       8            // feature pairs per CTA
#define NTHREADS 256
#define NCTAS    (F_FEAT / G) // 128

typedef unsigned long long u64;

// ---------- packed f32x2 helpers ----------
__device__ __forceinline__ u64 ffma2(u64 a, u64 b, u64 c) {
    u64 d;
    asm("fma.rn.f32x2 %0, %1, %2, %3;" : "=l"(d) : "l"(a), "l"(b), "l"(c));
    return d;
}
__device__ __forceinline__ u64 dup2(float x) {
    u64 r;
    asm("mov.b64 %0, {%1, %1};" : "=l"(r) : "f"(x));
    return r;
}
__device__ __forceinline__ float2 unpk(u64 v) {
    float2 r;
    asm("mov.b64 {%0, %1}, %2;" : "=f"(r.x), "=f"(r.y) : "l"(v));
    return r;
}
__device__ __forceinline__ u64 pack2(float x, float y) {
    u64 r;
    asm("mov.b64 %0, {%1, %2};" : "=l"(r) : "f"(x), "f"(y));
    return r;
}
__device__ __forceinline__ u64 tanh2(u64 v) {
    const float2 f = unpk(v);
    return pack2(tanhf(f.x), tanhf(f.y));
}
__device__ __forceinline__ float fast_sigmoid(float x) {
    return __fdividef(1.0f, 1.0f + __expf(-x));
}

// ---------- repacked (transposed) weights: coalesced mainloop loads ----------
// g_W1p[k4*256 + j] = float4 of W1[j][4k4..4k4+3]      (k4<32,  j<256)
// g_W2p[k4*128 + j] = float4 of W2[j][4k4..4k4+3]      (k4<64,  j<128)
// g_Whp[k4*384 + j] = float4 of W_hh[j][4k4..4k4+3]    (k4<32,  j<384)
__device__ float4 g_W1p[32 * 256];
__device__ float4 g_W2p[64 * 128];
__device__ float4 g_Whp[32 * 384];

__global__ void repack_kernel(const float* __restrict__ W1,
                              const float* __restrict__ W2,
                              const float* __restrict__ Whh)
{
    int i = blockIdx.x * blockDim.x + threadIdx.x;
    if (i < 32 * 256) {
        int k4 = i >> 8, j = i & 255;
        g_W1p[k4 * 256 + j] = *(const float4*)(W1 + j * LATENT + 4 * k4);
    } else if (i < 32 * 256 + 64 * 128) {
        int t = i - 32 * 256;
        int k4 = t >> 7, j = t & 127;
        g_W2p[k4 * 128 + j] = *(const float4*)(W2 + j * ODE_H + 4 * k4);
    } else if (i < 32 * 256 + 64 * 128 + 32 * 384) {
        int t = i - (32 * 256 + 64 * 128);
        int k4 = t / 384, j = t % 384;
        g_Whp[k4 * 384 + j] = *(const float4*)(Whh + j * LATENT + 4 * k4);
    }
}

// ---------- main persistent recurrence kernel ----------
__global__ __launch_bounds__(NTHREADS, 1)
void ode_rnn_kernel(const float* __restrict__ times,
                    const float* __restrict__ vals,
                    const float* __restrict__ mask,
                    const float* __restrict__ b1,
                    const float* __restrict__ b2,
                    const float* __restrict__ W_ih,
                    const float* __restrict__ b_ih,
                    const float* __restrict__ b_hh,
                    float* __restrict__ out)
{
    // h as interleaved feature pairs: hp[p*128 + k] = {h[2p][k], h[2p+1][k]}
    __shared__ __align__(16) u64 hp[GP * LATENT];          // 8 KB
    // pool reused: phase1 -> t1 pairs [p*256 + j]; phase3 -> gh pairs [p*384 + j]
    __shared__ __align__(16) u64 pool[GP * GR];            // 24 KB
    __shared__ float2 obs2[GP];
    __shared__ float2 m2[GP];

    const int tid = threadIdx.x;
    const int f0  = blockIdx.x * G;
    const bool gemv = (tid < 128);

    for (int idx = tid; idx < GP * LATENT; idx += NTHREADS)
        hp[idx] = 0ULL;
    __syncthreads();

    for (int i = 0; i < T_STEPS; ++i) {
        const int row = T_STEPS - 1 - i;               // reversed sequence
        float dt = 0.0f;
        if (i > 0) dt = __ldg(times + row + 1) - __ldg(times + row);

        if (tid < GP) {
            obs2[tid] = __ldg((const float2*)(vals + (long)row * F_FEAT + f0) + tid);
            m2[tid]   = __ldg((const float2*)(mask + (long)row * F_FEAT + f0) + tid);
        }

        if (dt > 0.0f) {
            // ---- Phase 1: t1[p][j] = tanh(b1[j] + sum_k h2[p][k]*W1[j][k])
            //      128 threads, JR=2 (rows tid, tid+128), all 8 pairs ----
            if (gemv) {
                const int j0 = tid, j1 = tid + 128;
                u64 a0[GP], a1[GP];
                const u64 bj0 = dup2(__ldg(b1 + j0));
                const u64 bj1 = dup2(__ldg(b1 + j1));
                #pragma unroll
                for (int p = 0; p < GP; ++p) { a0[p] = bj0; a1[p] = bj1; }
                #pragma unroll 4
                for (int k4 = 0; k4 < LATENT / 4; ++k4) {
                    const float4 wa = __ldg(g_W1p + k4 * ODE_H + j0);
                    const float4 wb = __ldg(g_W1p + k4 * ODE_H + j1);
                    const u64 wa0 = dup2(wa.x), wa1 = dup2(wa.y), wa2 = dup2(wa.z), wa3 = dup2(wa.w);
                    const u64 wb0 = dup2(wb.x), wb1 = dup2(wb.y), wb2 = dup2(wb.z), wb3 = dup2(wb.w);
                    #pragma unroll
                    for (int p = 0; p < GP; ++p) {
                        const ulonglong2* hv = (const ulonglong2*)(hp + p * LATENT);
                        const ulonglong2 x = hv[2 * k4];
                        const ulonglong2 y = hv[2 * k4 + 1];
                        a0[p] = ffma2(x.x, wa0, a0[p]); a1[p] = ffma2(x.x, wb0, a1[p]);
                        a0[p] = ffma2(x.y, wa1, a0[p]); a1[p] = ffma2(x.y, wb1, a1[p]);
                        a0[p] = ffma2(y.x, wa2, a0[p]); a1[p] = ffma2(y.x, wb2, a1[p]);
                        a0[p] = ffma2(y.y, wa3, a0[p]); a1[p] = ffma2(y.y, wb3, a1[p]);
                    }
                }
                #pragma unroll
                for (int p = 0; p < GP; ++p) {
                    pool[p * ODE_H + j0] = tanh2(a0[p]);
                    pool[p * ODE_H + j1] = tanh2(a1[p]);
                }
            }
            __syncthreads();

            // ---- Phase 2: h2[p][j] += dt * (b2[j] + sum_k t1[p][k]*W2[j][k])
            //      128 threads, JR=2 (rows jb, jb+64), 4 pairs each ----
            if (gemv) {
                const int jb = tid & 63;
                const int j0 = jb, j1 = jb + 64;
                const int p0 = (tid >> 6) * 4;
                u64 a0[4], a1[4];
                const u64 bj0 = dup2(__ldg(b2 + j0));
                const u64 bj1 = dup2(__ldg(b2 + j1));
                #pragma unroll
                for (int p = 0; p < 4; ++p) { a0[p] = bj0; a1[p] = bj1; }
                #pragma unroll 4
                for (int k4 = 0; k4 < ODE_H / 4; ++k4) {
                    const float4 wa = __ldg(g_W2p + k4 * LATENT + j0);
                    const float4 wb = __ldg(g_W2p + k4 * LATENT + j1);
                    const u64 wa0 = dup2(wa.x), wa1 = dup2(wa.y), wa2 = dup2(wa.z), wa3 = dup2(wa.w);
                    const u64 wb0 = dup2(wb.x), wb1 = dup2(wb.y), wb2 = dup2(wb.z), wb3 = dup2(wb.w);
                    #pragma unroll
                    for (int p = 0; p < 4; ++p) {
                        const ulonglong2* tv = (const ulonglong2*)(pool + (p0 + p) * ODE_H);
                        const ulonglong2 x = tv[2 * k4];
                        const ulonglong2 y = tv[2 * k4 + 1];
                        a0[p] = ffma2(x.x, wa0, a0[p]); a1[p] = ffma2(x.x, wb0, a1[p]);
                        a0[p] = ffma2(x.y, wa1, a0[p]); a1[p] = ffma2(x.y, wb1, a1[p]);
                        a0[p] = ffma2(y.x, wa2, a0[p]); a1[p] = ffma2(y.x, wb2, a1[p]);
                        a0[p] = ffma2(y.y, wa3, a0[p]); a1[p] = ffma2(y.y, wb3, a1[p]);
                    }
                }
                const u64 dt2 = dup2(dt);
                #pragma unroll
                for (int p = 0; p < 4; ++p) {
                    hp[(p0 + p) * LATENT + j0] = ffma2(a0[p], dt2, hp[(p0 + p) * LATENT + j0]);
                    hp[(p0 + p) * LATENT + j1] = ffma2(a1[p], dt2, hp[(p0 + p) * LATENT + j1]);
                }
            }
            __syncthreads();
        }

        // ---- Phase 3: gh[p][j] = b_hh[j] + sum_k h2[p][k]*W_hh[j][k] ----
        if (gemv) {
            {   // 3a: rows tid, tid+128 (JR=2, all 8 pairs)
                const int j0 = tid, j1 = tid + 128;
                u64 a0[GP], a1[GP];
                const u64 bj0 = dup2(__ldg(b_hh + j0));
                const u64 bj1 = dup2(__ldg(b_hh + j1));
                #pragma unroll
                for (int p = 0; p < GP; ++p) { a0[p] = bj0; a1[p] = bj1; }
                #pragma unroll 4
                for (int k4 = 0; k4 < LATENT / 4; ++k4) {
                    const float4 wa = __ldg(g_Whp + k4 * GR + j0);
                    const float4 wb = __ldg(g_Whp + k4 * GR + j1);
                    const u64 wa0 = dup2(wa.x), wa1 = dup2(wa.y), wa2 = dup2(wa.z), wa3 = dup2(wa.w);
                    const u64 wb0 = dup2(wb.x), wb1 = dup2(wb.y), wb2 = dup2(wb.z), wb3 = dup2(wb.w);
                    #pragma unroll
                    for (int p = 0; p < GP; ++p) {
                        const ulonglong2* hv = (const ulonglong2*)(hp + p * LATENT);
                        const ulonglong2 x = hv[2 * k4];
                        const ulonglong2 y = hv[2 * k4 + 1];
                        a0[p] = ffma2(x.x, wa0, a0[p]); a1[p] = ffma2(x.x, wb0, a1[p]);
                        a0[p] = ffma2(x.y, wa1, a0[p]); a1[p] = ffma2(x.y, wb1, a1[p]);
                        a0[p] = ffma2(y.x, wa2, a0[p]); a1[p] = ffma2(y.x, wb2, a1[p]);
                        a0[p] = ffma2(y.y, wa3, a0[p]); a1[p] = ffma2(y.y, wb3, a1[p]);
                    }
                }
                #pragma unroll
                for (int p = 0; p < GP; ++p) {
                    pool[p * GR + j0] = a0[p];
                    pool[p * GR + j1] = a1[p];
                }
            }
            {   // 3b: row 256 + tid (JR=1, all 8 pairs)
                const int j = 2 * LATENT + tid;
                u64 acc[GP];
                const u64 bj = dup2(__ldg(b_hh + j));
                #pragma unroll
                for (int p = 0; p < GP; ++p) acc[p] = bj;
                #pragma unroll 4
                for (int k4 = 0; k4 < LATENT / 4; ++k4) {
                    const float4 w = __ldg(g_Whp + k4 * GR + j);
                    const u64 w0 = dup2(w.x), w1 = dup2(w.y), w2 = dup2(w.z), w3 = dup2(w.w);
                    #pragma unroll
                    for (int p = 0; p < GP; ++p) {
                        const ulonglong2* hv = (const ulonglong2*)(hp + p * LATENT);
                        const ulonglong2 x = hv[2 * k4];
                        const ulonglong2 y = hv[2 * k4 + 1];
                        acc[p] = ffma2(x.x, w0, acc[p]);
                        acc[p] = ffma2(x.y, w1, acc[p]);
                        acc[p] = ffma2(y.x, w2, acc[p]);
                        acc[p] = ffma2(y.y, w3, acc[p]);
                    }
                }
                #pragma unroll
                for (int p = 0; p < GP; ++p)
                    pool[p * GR + j] = acc[p];
            }
        }
        __syncthreads();

        // ---- Update: GRU gates + mask mix over 1024 (pair, l) elements ----
        #pragma unroll
        for (int rep = 0; rep < (GP * LATENT) / NTHREADS; ++rep) {
            const int idx = rep * NTHREADS + tid;
            const int p = idx >> 7;
            const int l = idx & (LATENT - 1);
            const float2 gr = unpk(pool[p * GR + l]);
            const float2 gz = unpk(pool[p * GR + LATENT + l]);
            const float2 gn = unpk(pool[p * GR + 2 * LATENT + l]);
            const float2 ob = obs2[p];
            const float2 mm = m2[p];
            const float2 h  = unpk(hp[p * LATENT + l]);
            const float wr = __ldg(W_ih + l);
            const float wz = __ldg(W_ih + LATENT + l);
            const float wn = __ldg(W_ih + 2 * LATENT + l);
            const float br = __ldg(b_ih + l);
            const float bz = __ldg(b_ih + LATENT + l);
            const float bn = __ldg(b_ih + 2 * LATENT + l);

            const float rX = fast_sigmoid(fmaf(ob.x, wr, br) + gr.x);
            const float zX = fast_sigmoid(fmaf(ob.x, wz, bz) + gz.x);
            const float nX = tanhf(fmaf(ob.x, wn, bn) + rX * gn.x);
            const float hcX = fmaf(zX, h.x - nX, nX);
            const float hX  = fmaf(mm.x, hcX - h.x, h.x);

            const float rY = fast_sigmoid(fmaf(ob.y, wr, br) + gr.y);
            const float zY = fast_sigmoid(fmaf(ob.y, wz, bz) + gz.y);
            const float nY = tanhf(fmaf(ob.y, wn, bn) + rY * gn.y);
            const float hcY = fmaf(zY, h.y - nY, nY);
            const float hY  = fmaf(mm.y, hcY - h.y, h.y);

            hp[p * LATENT + l] = pack2(hX, hY);
        }
        __syncthreads();
    }

    for (int idx = tid; idx < GP * LATENT; idx += NTHREADS) {
        const int p = idx >> 7;
        const int l = idx & (LATENT - 1);
        const float2 v = unpk(hp[idx]);
        out[(long)(f0 + 2 * p)     * LATENT + l] = v.x;
        out[(long)(f0 + 2 * p + 1) * LATENT + l] = v.y;
    }
}

extern "C" void kernel_launch(void* const* d_in, const int* in_sizes, int n_in,
                              void* d_out, int out_size)
{
    (void)in_sizes; (void)n_in; (void)out_size;
    const float* times = (const float*)d_in[0];
    const float* vals  = (const float*)d_in[1];
    const float* mask  = (const float*)d_in[2];
    const float* W1    = (const float*)d_in[3];
    const float* b1    = (const float*)d_in[4];
    const float* W2    = (const float*)d_in[5];
    const float* b2    = (const float*)d_in[6];
    const float* W_ih  = (const float*)d_in[7];
    const float* b_ih  = (const float*)d_in[8];
    const float* W_hh  = (const float*)d_in[9];
    const float* b_hh  = (const float*)d_in[10];
    float* out = (float*)d_out;

    const int total = 32 * 256 + 64 * 128 + 32 * 384;
    repack_kernel<<<(total + 255) / 256, 256>>>(W1, W2, W_hh);
    ode_rnn_kernel<<<NCTAS, NTHREADS>>>(times, vals, mask,
                                        b1, b2, W_ih, b_ih, b_hh, out);
}

// round 4
// speedup vs baseline: 2.2383x; 1.1030x over previous
#include <cuda_runtime.h>

#define T_STEPS  1024
#define F_FEAT   2048
#define LATENT   128
#define ODE_H    256
#define GR       384          // 3*LATENT gate rows
#define G        16           // features per CTA
#define GP       8            // feature pairs per CTA
#define GPG      4            // feature pairs per group
#define NTHREADS 256
#define NCTAS    (F_FEAT / G) // 128

typedef unsigned long long u64;

// ---------- packed f32x2 helpers ----------
__device__ __forceinline__ u64 ffma2(u64 a, u64 b, u64 c) {
    u64 d;
    asm("fma.rn.f32x2 %0, %1, %2, %3;" : "=l"(d) : "l"(a), "l"(b), "l"(c));
    return d;
}
__device__ __forceinline__ u64 dup2(float x) {
    u64 r;
    asm("mov.b64 %0, {%1, %1};" : "=l"(r) : "f"(x));
    return r;
}
__device__ __forceinline__ float2 unpk(u64 v) {
    float2 r;
    asm("mov.b64 {%0, %1}, %2;" : "=f"(r.x), "=f"(r.y) : "l"(v));
    return r;
}
__device__ __forceinline__ u64 pack2(float x, float y) {
    u64 r;
    asm("mov.b64 %0, {%1, %2};" : "=l"(r) : "f"(x), "f"(y));
    return r;
}
__device__ __forceinline__ u64 tanh2(u64 v) {
    const float2 f = unpk(v);
    return pack2(tanhf(f.x), tanhf(f.y));
}
__device__ __forceinline__ float fast_sigmoid(float x) {
    return __fdividef(1.0f, 1.0f + __expf(-x));
}
#define GBAR(id) asm volatile("bar.sync %0, 128;" :: "r"(id) : "memory")

// ---------- repacked (transposed) weights: coalesced mainloop loads ----------
__device__ float4 g_W1p[32 * 256];   // [k4*256 + j] = W1[j][4k4..]
__device__ float4 g_W2p[64 * 128];   // [k4*128 + j] = W2[j][4k4..]
__device__ float4 g_Whp[32 * 384];   // [k4*384 + j] = W_hh[j][4k4..]

__global__ void repack_kernel(const float* __restrict__ W1,
                              const float* __restrict__ W2,
                              const float* __restrict__ Whh)
{
    int i = blockIdx.x * blockDim.x + threadIdx.x;
    if (i < 32 * 256) {
        int k4 = i >> 8, j = i & 255;
        g_W1p[k4 * 256 + j] = *(const float4*)(W1 + j * LATENT + 4 * k4);
    } else if (i < 32 * 256 + 64 * 128) {
        int t = i - 32 * 256;
        int k4 = t >> 7, j = t & 127;
        g_W2p[k4 * 128 + j] = *(const float4*)(W2 + j * ODE_H + 4 * k4);
    } else if (i < 32 * 256 + 64 * 128 + 32 * 384) {
        int t = i - (32 * 256 + 64 * 128);
        int k4 = t / 384, j = t % 384;
        g_Whp[k4 * 384 + j] = *(const float4*)(Whh + j * LATENT + 4 * k4);
    }
}

// ---------- main persistent recurrence kernel ----------
__global__ __launch_bounds__(NTHREADS, 1)
void ode_rnn_kernel(const float* __restrict__ times,
                    const float* __restrict__ vals,
                    const float* __restrict__ mask,
                    const float* __restrict__ b1,
                    const float* __restrict__ b2,
                    const float* __restrict__ W_ih,
                    const float* __restrict__ b_ih,
                    const float* __restrict__ b_hh,
                    float* __restrict__ out)
{
    // two independent groups; each owns 4 feature-pairs
    __shared__ __align__(16) u64 hp[GP * LATENT];    // 8 KB  (group g: [g*512 .. ))
    __shared__ __align__(16) u64 pool[GP * GR];      // 24 KB (group g: [g*1536 .. ))
    __shared__ float2 obs2[GP];
    __shared__ float2 m2[GP];

    const int tid = threadIdx.x;
    const int grp = tid >> 7;              // 0 or 1
    const int lt  = tid & 127;             // lane within group
    const int bar = grp + 1;               // named barrier id
    const int f0  = blockIdx.x * G;
    u64* __restrict__ hpg   = hp   + grp * GPG * LATENT;
    u64* __restrict__ poolg = pool + grp * GPG * GR;
    const int pb = grp * GPG;              // global pair base for staging

    for (int idx = tid; idx < GP * LATENT; idx += NTHREADS)
        hp[idx] = 0ULL;
    __syncthreads();

    for (int i = 0; i < T_STEPS; ++i) {
        const int row = T_STEPS - 1 - i;               // reversed sequence
        float dt = 0.0f;
        if (i > 0) dt = __ldg(times + row + 1) - __ldg(times + row);

        if (lt < GPG) {
            obs2[pb + lt] = __ldg((const float2*)(vals + (long)row * F_FEAT + f0) + pb + lt);
            m2[pb + lt]   = __ldg((const float2*)(mask + (long)row * F_FEAT + f0) + pb + lt);
        }

        if (dt > 0.0f) {
            // ---- Phase 1: t1[p][j] = tanh(b1[j] + sum_k h2[p][k]*W1[j][k])
            //      JR=2 (rows lt, lt+128), 4 pairs ----
            {
                const int j0 = lt, j1 = lt + 128;
                u64 a0[GPG], a1[GPG];
                const u64 bj0 = dup2(__ldg(b1 + j0));
                const u64 bj1 = dup2(__ldg(b1 + j1));
                #pragma unroll
                for (int p = 0; p < GPG; ++p) { a0[p] = bj0; a1[p] = bj1; }
                #pragma unroll 4
                for (int k4 = 0; k4 < LATENT / 4; ++k4) {
                    const float4 wa = __ldg(g_W1p + k4 * ODE_H + j0);
                    const float4 wb = __ldg(g_W1p + k4 * ODE_H + j1);
                    const u64 wa0 = dup2(wa.x), wa1 = dup2(wa.y), wa2 = dup2(wa.z), wa3 = dup2(wa.w);
                    const u64 wb0 = dup2(wb.x), wb1 = dup2(wb.y), wb2 = dup2(wb.z), wb3 = dup2(wb.w);
                    #pragma unroll
                    for (int p = 0; p < GPG; ++p) {
                        const ulonglong2* hv = (const ulonglong2*)(hpg + p * LATENT);
                        const ulonglong2 x = hv[2 * k4];
                        const ulonglong2 y = hv[2 * k4 + 1];
                        a0[p] = ffma2(x.x, wa0, a0[p]); a1[p] = ffma2(x.x, wb0, a1[p]);
                        a0[p] = ffma2(x.y, wa1, a0[p]); a1[p] = ffma2(x.y, wb1, a1[p]);
                        a0[p] = ffma2(y.x, wa2, a0[p]); a1[p] = ffma2(y.x, wb2, a1[p]);
                        a0[p] = ffma2(y.y, wa3, a0[p]); a1[p] = ffma2(y.y, wb3, a1[p]);
                    }
                }
                #pragma unroll
                for (int p = 0; p < GPG; ++p) {
                    poolg[p * ODE_H + j0] = tanh2(a0[p]);
                    poolg[p * ODE_H + j1] = tanh2(a1[p]);
                }
            }
            GBAR(bar);

            // ---- Phase 2: h2[p][j] += dt * (b2[j] + sum_k t1[p][k]*W2[j][k])
            //      JR=1 (row lt), 4 pairs ----
            {
                const int j = lt;
                u64 acc[GPG];
                const u64 bj = dup2(__ldg(b2 + j));
                #pragma unroll
                for (int p = 0; p < GPG; ++p) acc[p] = bj;
                #pragma unroll 4
                for (int k4 = 0; k4 < ODE_H / 4; ++k4) {
                    const float4 w = __ldg(g_W2p + k4 * LATENT + j);
                    const u64 w0 = dup2(w.x), w1 = dup2(w.y), w2 = dup2(w.z), w3 = dup2(w.w);
                    #pragma unroll
                    for (int p = 0; p < GPG; ++p) {
                        const ulonglong2* tv = (const ulonglong2*)(poolg + p * ODE_H);
                        const ulonglong2 x = tv[2 * k4];
                        const ulonglong2 y = tv[2 * k4 + 1];
                        acc[p] = ffma2(x.x, w0, acc[p]);
                        acc[p] = ffma2(x.y, w1, acc[p]);
                        acc[p] = ffma2(y.x, w2, acc[p]);
                        acc[p] = ffma2(y.y, w3, acc[p]);
                    }
                }
                const u64 dt2 = dup2(dt);
                #pragma unroll
                for (int p = 0; p < GPG; ++p)
                    hpg[p * LATENT + j] = ffma2(acc[p], dt2, hpg[p * LATENT + j]);
            }
            GBAR(bar);
        }

        // ---- Phase 3: gh[p][j] = b_hh[j] + sum_k h2[p][k]*W_hh[j][k]
        //      JR=3 (rows lt, lt+128, lt+256), 4 pairs ----
        {
            const int j0 = lt, j1 = lt + 128, j2 = lt + 256;
            u64 a0[GPG], a1[GPG], a2[GPG];
            const u64 bj0 = dup2(__ldg(b_hh + j0));
            const u64 bj1 = dup2(__ldg(b_hh + j1));
            const u64 bj2 = dup2(__ldg(b_hh + j2));
            #pragma unroll
            for (int p = 0; p < GPG; ++p) { a0[p] = bj0; a1[p] = bj1; a2[p] = bj2; }
            #pragma unroll 4
            for (int k4 = 0; k4 < LATENT / 4; ++k4) {
                const float4 wa = __ldg(g_Whp + k4 * GR + j0);
                const float4 wb = __ldg(g_Whp + k4 * GR + j1);
                const float4 wc = __ldg(g_Whp + k4 * GR + j2);
                const u64 wa0 = dup2(wa.x), wa1 = dup2(wa.y), wa2 = dup2(wa.z), wa3 = dup2(wa.w);
                const u64 wb0 = dup2(wb.x), wb1 = dup2(wb.y), wb2 = dup2(wb.z), wb3 = dup2(wb.w);
                const u64 wc0 = dup2(wc.x), wc1 = dup2(wc.y), wc2 = dup2(wc.z), wc3 = dup2(wc.w);
                #pragma unroll
                for (int p = 0; p < GPG; ++p) {
                    const ulonglong2* hv = (const ulonglong2*)(hpg + p * LATENT);
                    const ulonglong2 x = hv[2 * k4];
                    const ulonglong2 y = hv[2 * k4 + 1];
                    a0[p] = ffma2(x.x, wa0, a0[p]); a1[p] = ffma2(x.x, wb0, a1[p]); a2[p] = ffma2(x.x, wc0, a2[p]);
                    a0[p] = ffma2(x.y, wa1, a0[p]); a1[p] = ffma2(x.y, wb1, a1[p]); a2[p] = ffma2(x.y, wc1, a2[p]);
                    a0[p] = ffma2(y.x, wa2, a0[p]); a1[p] = ffma2(y.x, wb2, a1[p]); a2[p] = ffma2(y.x, wc2, a2[p]);
                    a0[p] = ffma2(y.y, wa3, a0[p]); a1[p] = ffma2(y.y, wb3, a1[p]); a2[p] = ffma2(y.y, wc3, a2[p]);
                }
            }
            #pragma unroll
            for (int p = 0; p < GPG; ++p) {
                poolg[p * GR + j0] = a0[p];
                poolg[p * GR + j1] = a1[p];
                poolg[p * GR + j2] = a2[p];
            }
        }
        GBAR(bar);

        // ---- Update: GRU gates + mask mix (512 pair-elems per group) ----
        #pragma unroll
        for (int rep = 0; rep < (GPG * LATENT) / 128; ++rep) {
            const int idx = rep * 128 + lt;
            const int p = idx >> 7;               // local pair 0..3
            const int l = idx & (LATENT - 1);
            const float2 gr = unpk(poolg[p * GR + l]);
            const float2 gz = unpk(poolg[p * GR + LATENT + l]);
            const float2 gn = unpk(poolg[p * GR + 2 * LATENT + l]);
            const float2 ob = obs2[pb + p];
            const float2 mm = m2[pb + p];
            const float2 h  = unpk(hpg[p * LATENT + l]);
            const float wr = __ldg(W_ih + l);
            const float wz = __ldg(W_ih + LATENT + l);
            const float wn = __ldg(W_ih + 2 * LATENT + l);
            const float br = __ldg(b_ih + l);
            const float bz = __ldg(b_ih + LATENT + l);
            const float bn = __ldg(b_ih + 2 * LATENT + l);

            const float rX = fast_sigmoid(fmaf(ob.x, wr, br) + gr.x);
            const float zX = fast_sigmoid(fmaf(ob.x, wz, bz) + gz.x);
            const float nX = tanhf(fmaf(ob.x, wn, bn) + rX * gn.x);
            const float hcX = fmaf(zX, h.x - nX, nX);
            const float hX  = fmaf(mm.x, hcX - h.x, h.x);

            const float rY = fast_sigmoid(fmaf(ob.y, wr, br) + gr.y);
            const float zY = fast_sigmoid(fmaf(ob.y, wz, bz) + gz.y);
            const float nY = tanhf(fmaf(ob.y, wn, bn) + rY * gn.y);
            const float hcY = fmaf(zY, h.y - nY, nY);
            const float hY  = fmaf(mm.y, hcY - h.y, h.y);

            hpg[p * LATENT + l] = pack2(hX, hY);
        }
        GBAR(bar);
    }

    // write final h for this group's 4 pairs
    for (int rep = 0; rep < (GPG * LATENT) / 128; ++rep) {
        const int idx = rep * 128 + lt;
        const int p = idx >> 7;
        const int l = idx & (LATENT - 1);
        const float2 v = unpk(hpg[p * LATENT + l]);
        out[(long)(f0 + 2 * (pb + p))     * LATENT + l] = v.x;
        out[(long)(f0 + 2 * (pb + p) + 1) * LATENT + l] = v.y;
    }
}

extern "C" void kernel_launch(void* const* d_in, const int* in_sizes, int n_in,
                              void* d_out, int out_size)
{
    (void)in_sizes; (void)n_in; (void)out_size;
    const float* times = (const float*)d_in[0];
    const float* vals  = (const float*)d_in[1];
    const float* mask  = (const float*)d_in[2];
    const float* W1    = (const float*)d_in[3];
    const float* b1    = (const float*)d_in[4];
    const float* W2    = (const float*)d_in[5];
    const float* b2    = (const float*)d_in[6];
    const float* W_ih  = (const float*)d_in[7];
    const float* b_ih  = (const float*)d_in[8];
    const float* W_hh  = (const float*)d_in[9];
    const float* b_hh  = (const float*)d_in[10];
    float* out = (float*)d_out;

    const int total = 32 * 256 + 64 * 128 + 32 * 384;
    repack_kernel<<<(total + 255) / 256, 256>>>(W1, W2, W_hh);
    ode_rnn_kernel<<<NCTAS, NTHREADS>>>(times, vals, mask,
                                        b1, b2, W_ih, b_ih, b_hh, out);
}